// round 3
// baseline (speedup 1.0000x reference)
#include <cuda_runtime.h>
#include <cuda_fp16.h>
#include <math.h>
#include <stdint.h>

#define HDIM 768
#define NHEAD 12
#define DHEAD 64
#define BS 8
#define TLEN 64
#define ILEN 197
#define MTEXT (BS*TLEN)      // 512
#define MIMG  (BS*ILEN)      // 1576
#define MGATE (MTEXT*ILEN)   // 100864 = 788*128 exactly

// ---------------- scratch (static device memory; no allocation) ----------------
__device__ __half g_wT[6][HDIM*HDIM];       // transposed fp16 weights: 0:Wt 1:Wq 2:Wi 3:Wk 4:Wv 5:W1  ([N][K])
__device__ __half g_small[2][MTEXT*HDIM];   // 0: text_emb, 1: q
__device__ __half g_big[3][MIMG*HDIM];      // 0: image_emb, 1: k, 2: v
__device__ float  g_gate[MGATE];

// ---------------- mma.sync m16n8k16 fp16 -> fp32 ----------------
__device__ __forceinline__ void mma_f16(float c[4], uint32_t a0, uint32_t a1, uint32_t a2, uint32_t a3,
                                        uint32_t b0, uint32_t b1) {
    asm volatile(
        "mma.sync.aligned.m16n8k16.row.col.f32.f16.f16.f32 "
        "{%0,%1,%2,%3},{%4,%5,%6,%7},{%8,%9},{%0,%1,%2,%3};\n"
        : "+f"(c[0]), "+f"(c[1]), "+f"(c[2]), "+f"(c[3])
        : "r"(a0), "r"(a1), "r"(a2), "r"(a3), "r"(b0), "r"(b1));
}

// ---------------- prep: transpose + fp32->fp16 convert for 6 weight matrices ----------------
__global__ void prep_transpose(const float* __restrict__ Wt_, const float* __restrict__ Wq_,
                               const float* __restrict__ Wi_, const float* __restrict__ Wk_,
                               const float* __restrict__ Wv_, const float* __restrict__ W1_) {
    __shared__ float tile[32][33];
    int which = blockIdx.z;
    const float* src = (which == 0) ? Wt_ : (which == 1) ? Wq_ : (which == 2) ? Wi_
                     : (which == 3) ? Wk_ : (which == 4) ? Wv_ : W1_;
    __half* dst = g_wT[which];
    int k0 = blockIdx.y * 32, n0 = blockIdx.x * 32;
    #pragma unroll
    for (int r = threadIdx.y; r < 32; r += 8)
        tile[r][threadIdx.x] = src[(k0 + r) * HDIM + n0 + threadIdx.x];
    __syncthreads();
    #pragma unroll
    for (int r = threadIdx.y; r < 32; r += 8)
        dst[(size_t)(n0 + r) * HDIM + k0 + threadIdx.x] = __float2half(tile[threadIdx.x][r]);
}

// ---------------- fused projections: all 5 GEMMs in one launch ----------------
// blockIdx.z selects GEMM: 0:text->Wt(emb) 1:text->Wq(q) 2:image->Wi(emb) 3:image->Wk(k) 4:image->Wv(v)
// C[M,768] = f16(A[M,768] @ W + b), W given as W^T fp16 [N][K]
#define PJ_ST 72  // smem row stride in halves (64 + 8 pad)
__global__ __launch_bounds__(128) void proj_all(const float* __restrict__ text,
                                                const float* __restrict__ image,
                                                const float* __restrict__ bt,
                                                const float* __restrict__ bq,
                                                const float* __restrict__ bi,
                                                const float* __restrict__ bk,
                                                const float* __restrict__ bv) {
    int g = blockIdx.z;
    const float* A;
    const float* bias;
    __half* out;
    int M;
    if (g == 0)      { A = text;  bias = bt; out = g_small[0]; M = MTEXT; }
    else if (g == 1) { A = text;  bias = bq; out = g_small[1]; M = MTEXT; }
    else if (g == 2) { A = image; bias = bi; out = g_big[0];   M = MIMG; }
    else if (g == 3) { A = image; bias = bk; out = g_big[1];   M = MIMG; }
    else             { A = image; bias = bv; out = g_big[2];   M = MIMG; }
    int m0 = blockIdx.x * 64;
    if (m0 >= M) return;                      // whole CTA exits (text GEMMs use 8 of 25 m-blocks)
    const __half* W = g_wT[g];

    __shared__ __half As[64 * PJ_ST];
    __shared__ __half Ws[64 * PJ_ST];         // [n][k]
    int n0 = blockIdx.y * 64;
    int tid = threadIdx.x, lane = tid & 31, warp = tid >> 5;
    int wm = (warp >> 1) * 32, wn = (warp & 1) * 32;

    float acc[2][4][4];
    #pragma unroll
    for (int i = 0; i < 2; i++)
        #pragma unroll
        for (int j = 0; j < 4; j++)
            #pragma unroll
            for (int x = 0; x < 4; x++) acc[i][j][x] = 0.f;

    for (int k0 = 0; k0 < HDIM; k0 += 64) {
        #pragma unroll
        for (int l = 0; l < 16; l++) {
            int idx = l * 128 + tid;
            int r = idx >> 5, c2 = idx & 31;
            int m = m0 + r;
            float2 v = (m < M) ? *(const float2*)(A + (size_t)m * HDIM + k0 + c2 * 2)
                               : make_float2(0.f, 0.f);
            *(__half2*)(As + r * PJ_ST + c2 * 2) = __floats2half2_rn(v.x, v.y);
        }
        #pragma unroll
        for (int l = 0; l < 16; l++) {
            int idx = l * 128 + tid;
            int r = idx >> 5, c2 = idx & 31;
            *(__half2*)(Ws + r * PJ_ST + c2 * 2) =
                *(const __half2*)(W + (size_t)(n0 + r) * HDIM + k0 + c2 * 2);
        }
        __syncthreads();
        #pragma unroll
        for (int kk = 0; kk < 64; kk += 16) {
            uint32_t af[2][4], bf[4][2];
            #pragma unroll
            for (int mt = 0; mt < 2; mt++) {
                const __half* base = As + (wm + mt * 16 + (lane >> 2)) * PJ_ST + kk + (lane & 3) * 2;
                af[mt][0] = *(const uint32_t*)(base);
                af[mt][1] = *(const uint32_t*)(base + 8 * PJ_ST);
                af[mt][2] = *(const uint32_t*)(base + 8);
                af[mt][3] = *(const uint32_t*)(base + 8 * PJ_ST + 8);
            }
            #pragma unroll
            for (int nt = 0; nt < 4; nt++) {
                const __half* base = Ws + (wn + nt * 8 + (lane >> 2)) * PJ_ST + kk + (lane & 3) * 2;
                bf[nt][0] = *(const uint32_t*)(base);
                bf[nt][1] = *(const uint32_t*)(base + 8);
            }
            #pragma unroll
            for (int mt = 0; mt < 2; mt++)
                #pragma unroll
                for (int nt = 0; nt < 4; nt++)
                    mma_f16(acc[mt][nt], af[mt][0], af[mt][1], af[mt][2], af[mt][3],
                            bf[nt][0], bf[nt][1]);
        }
        __syncthreads();
    }
    // epilogue: + bias, store fp16
    #pragma unroll
    for (int mt = 0; mt < 2; mt++) {
        int r0 = m0 + wm + mt * 16 + (lane >> 2);
        #pragma unroll
        for (int nt = 0; nt < 4; nt++) {
            int c = n0 + wn + nt * 8 + (lane & 3) * 2;
            float b0 = bias[c], b1v = bias[c + 1];
            if (r0 < M)
                *(__half2*)(out + (size_t)r0 * HDIM + c) =
                    __floats2half2_rn(acc[mt][nt][0] + b0, acc[mt][nt][1] + b1v);
            if (r0 + 8 < M)
                *(__half2*)(out + (size_t)(r0 + 8) * HDIM + c) =
                    __floats2half2_rn(acc[mt][nt][2] + b0, acc[mt][nt][3] + b1v);
        }
    }
}

// ---------------- fused gate kernel v2 ----------------
// Per CTA: 128 consecutive m-rows (m = (b*64+t)*197 + i).
// Phase 1: build A[m,k] = text_emb[t,k]*image_emb[b*197+i,k] ONCE into smem (128 x 768 fp16).
// Phase 2: for each 128-col n-chunk of W1^T: k-loop over resident A with
//          register-prefetched W tiles; fold +b1, relu, dot W2 into z partials.
// gate[m] = sigmoid(z + b2)
#define AST 776                       // A row stride in halves (768 + 8): 388 words, 388%32=4 -> conflict-free
#define WST 72                        // W tile row stride in halves
#define GATE_SMEM_BYTES (size_t)((128*AST + 128*WST) * sizeof(__half))
__global__ __launch_bounds__(512, 1) void gate_kernel(const float* __restrict__ b1,
                                                      const float* __restrict__ W2,
                                                      const float* __restrict__ pb2) {
    extern __shared__ __half dsm[];
    __half* As = dsm;                 // [128][AST]
    __half* Ws = dsm + 128 * AST;     // [128][WST]  ([n][k])
    __shared__ float s_z[128];

    int tid = threadIdx.x, lane = tid & 31, warp = tid >> 5;
    int m0 = blockIdx.x * 128;
    if (tid < 128) s_z[tid] = 0.f;

    const __half* W1t = g_wT[5];
    const __half* te = g_small[0];
    const __half* im = g_big[0];

    // -------- Phase 1: build A tile (each quad: one row, 4-word interleave) --------
    {
        int r = tid >> 2;                 // 0..127
        int m = m0 + r;
        int tr = m / ILEN;                // b*64 + t
        int ir = m - tr * ILEN;           // i
        const __half* trow = te + (size_t)tr * HDIM;
        const __half* irow = im + (size_t)((tr >> 6) * ILEN + ir) * HDIM;
        __half* arow = As + r * AST;
        int c0 = (tid & 3);
        #pragma unroll
        for (int j = 0; j < 96; j++) {
            int c2 = j * 4 + c0;          // half2 index 0..383
            __half2 tv = *(const __half2*)(trow + c2 * 2);
            __half2 iv = *(const __half2*)(irow + c2 * 2);
            *(__half2*)(arow + c2 * 2) = __hmul2(tv, iv);
        }
    }
    __syncthreads();

    // -------- Phase 2: GEMM over resident A --------
    // 16 warps as 4(m) x 4(n); each warp: 32m x 32n per n-chunk
    int wm = (warp >> 2) * 32, wn = (warp & 3) * 32;
    float zp[4] = {0.f, 0.f, 0.f, 0.f};

    for (int n0 = 0; n0 < HDIM; n0 += 128) {
        float acc[2][4][4];
        #pragma unroll
        for (int i = 0; i < 2; i++)
            #pragma unroll
            for (int j = 0; j < 4; j++)
                #pragma unroll
                for (int x = 0; x < 4; x++) acc[i][j][x] = 0.f;

        // preload W tile k0=0 into regs (8 x uint32 / thread = 128n x 64k tile)
        uint32_t wreg[8];
        #pragma unroll
        for (int l = 0; l < 8; l++) {
            int idx = l * 512 + tid;
            int r = idx >> 5, c2 = idx & 31;
            wreg[l] = *(const uint32_t*)(W1t + (size_t)(n0 + r) * HDIM + c2 * 2);
        }

        for (int k0 = 0; k0 < HDIM; k0 += 64) {
            // commit current regs to smem
            #pragma unroll
            for (int l = 0; l < 8; l++) {
                int idx = l * 512 + tid;
                int r = idx >> 5, c2 = idx & 31;
                *(uint32_t*)(Ws + r * WST + c2 * 2) = wreg[l];
            }
            __syncthreads();
            // prefetch next W tile while mma runs
            if (k0 + 64 < HDIM) {
                #pragma unroll
                for (int l = 0; l < 8; l++) {
                    int idx = l * 512 + tid;
                    int r = idx >> 5, c2 = idx & 31;
                    wreg[l] = *(const uint32_t*)(W1t + (size_t)(n0 + r) * HDIM + (k0 + 64) + c2 * 2);
                }
            }
            #pragma unroll
            for (int kk = 0; kk < 64; kk += 16) {
                uint32_t af[2][4], bf[4][2];
                #pragma unroll
                for (int mt = 0; mt < 2; mt++) {
                    const __half* base = As + (wm + mt * 16 + (lane >> 2)) * AST + (k0 + kk) + (lane & 3) * 2;
                    af[mt][0] = *(const uint32_t*)(base);
                    af[mt][1] = *(const uint32_t*)(base + 8 * AST);
                    af[mt][2] = *(const uint32_t*)(base + 8);
                    af[mt][3] = *(const uint32_t*)(base + 8 * AST + 8);
                }
                #pragma unroll
                for (int nt = 0; nt < 4; nt++) {
                    const __half* base = Ws + (wn + nt * 8 + (lane >> 2)) * WST + kk + (lane & 3) * 2;
                    bf[nt][0] = *(const uint32_t*)(base);
                    bf[nt][1] = *(const uint32_t*)(base + 8);
                }
                #pragma unroll
                for (int mt = 0; mt < 2; mt++)
                    #pragma unroll
                    for (int nt = 0; nt < 4; nt++)
                        mma_f16(acc[mt][nt], af[mt][0], af[mt][1], af[mt][2], af[mt][3],
                                bf[nt][0], bf[nt][1]);
            }
            __syncthreads();
        }
        // fold: + b1, relu, * W2 -> z partials
        #pragma unroll
        for (int mt = 0; mt < 2; mt++) {
            #pragma unroll
            for (int nt = 0; nt < 4; nt++) {
                int c = n0 + wn + nt * 8 + (lane & 3) * 2;
                float bb0 = __ldg(b1 + c), bb1 = __ldg(b1 + c + 1);
                float w0 = __ldg(W2 + c), w1 = __ldg(W2 + c + 1);
                float y00 = fmaxf(acc[mt][nt][0] + bb0, 0.f);
                float y01 = fmaxf(acc[mt][nt][1] + bb1, 0.f);
                float y10 = fmaxf(acc[mt][nt][2] + bb0, 0.f);
                float y11 = fmaxf(acc[mt][nt][3] + bb1, 0.f);
                zp[2 * mt + 0] += y00 * w0 + y01 * w1;
                zp[2 * mt + 1] += y10 * w0 + y11 * w1;
            }
        }
    }
    // reduce z: 16 threads contribute per row (4 lane-groups x 4 n-warps)
    int r0 = wm + (lane >> 2);
    atomicAdd(&s_z[r0],      zp[0]);
    atomicAdd(&s_z[r0 + 8],  zp[1]);
    atomicAdd(&s_z[r0 + 16], zp[2]);
    atomicAdd(&s_z[r0 + 24], zp[3]);
    __syncthreads();
    if (tid < 128) {
        float z = s_z[tid] + pb2[0];
        g_gate[m0 + tid] = 1.f / (1.f + __expf(-z));
    }
}

// ---------------- attention: scores, softmax, *gate, ctx ----------------
__global__ __launch_bounds__(256) void attn_kernel(float* __restrict__ out) {
    __shared__ __half vs[ILEN * 66];
    __shared__ float ps[8][ILEN];
    __shared__ float qs[8][DHEAD];
    int tid = threadIdx.x, lane = tid & 31, warp = tid >> 5;
    int bh = blockIdx.x;
    int b = bh / NHEAD, h = bh % NHEAD;
    const __half* kg = g_big[1];
    const __half* vg = g_big[2];
    const __half* qg = g_small[1];

    // stage V tile into smem
    for (int idx = tid; idx < ILEN * 32; idx += 256) {
        int i = idx >> 5, c2 = idx & 31;
        *(__half2*)(vs + i * 66 + c2 * 2) =
            *(const __half2*)(vg + (size_t)(b * ILEN + i) * HDIM + h * DHEAD + c2 * 2);
    }
    __syncthreads();

    for (int t = warp; t < TLEN; t += 8) {
        // q row -> smem
        {
            __half2 qv = *(const __half2*)(qg + (size_t)(b * TLEN + t) * HDIM + h * DHEAD + lane * 2);
            qs[warp][lane * 2] = __low2float(qv);
            qs[warp][lane * 2 + 1] = __high2float(qv);
        }
        __syncwarp();
        // scores for this t; lanes stride i
        float sv[7];
        float smax = -1e30f;
        #pragma unroll
        for (int ii = 0; ii < 7; ii++) {
            int i = lane + ii * 32;
            float s = -1e30f;
            if (i < ILEN) {
                const __half* krow = kg + (size_t)(b * ILEN + i) * HDIM + h * DHEAD;
                float a = 0.f;
                #pragma unroll
                for (int d = 0; d < DHEAD; d += 2) {
                    __half2 k2 = *(const __half2*)(krow + d);
                    a += qs[warp][d] * __low2float(k2) + qs[warp][d + 1] * __high2float(k2);
                }
                s = a * 0.125f;
            }
            sv[ii] = s;
            smax = fmaxf(smax, s);
        }
        #pragma unroll
        for (int o = 16; o; o >>= 1) smax = fmaxf(smax, __shfl_xor_sync(0xffffffffu, smax, o));
        float ssum = 0.f;
        #pragma unroll
        for (int ii = 0; ii < 7; ii++) {
            int i = lane + ii * 32;
            float e = (i < ILEN) ? __expf(sv[ii] - smax) : 0.f;
            sv[ii] = e;
            ssum += e;
        }
        #pragma unroll
        for (int o = 16; o; o >>= 1) ssum += __shfl_xor_sync(0xffffffffu, ssum, o);
        float inv = 1.f / ssum;
        int gbase = (b * TLEN + t) * ILEN;
        #pragma unroll
        for (int ii = 0; ii < 7; ii++) {
            int i = lane + ii * 32;
            if (i < ILEN) ps[warp][i] = sv[ii] * inv * g_gate[gbase + i];
        }
        __syncwarp();
        // ctx: lanes over d pairs
        float a0 = 0.f, a1 = 0.f;
        #pragma unroll 4
        for (int i = 0; i < ILEN; i++) {
            float p = ps[warp][i];
            __half2 v2 = *(const __half2*)(vs + i * 66 + lane * 2);
            a0 += p * __low2float(v2);
            a1 += p * __high2float(v2);
        }
        size_t obase = (size_t)(b * TLEN + t) * HDIM + h * DHEAD + lane * 2;
        out[obase] = a0;
        out[obase + 1] = a1;
        __syncwarp();
    }
}

// ---------------- launch ----------------
extern "C" void kernel_launch(void* const* d_in, const int* in_sizes, int n_in,
                              void* d_out, int out_size) {
    (void)in_sizes; (void)n_in; (void)out_size;
    const float* text  = (const float*)d_in[0];
    const float* image = (const float*)d_in[1];
    const float* Wq = (const float*)d_in[2];  const float* bq = (const float*)d_in[3];
    const float* Wk = (const float*)d_in[4];  const float* bk = (const float*)d_in[5];
    const float* Wv = (const float*)d_in[6];  const float* bv = (const float*)d_in[7];
    const float* Wt = (const float*)d_in[8];  const float* bt = (const float*)d_in[9];
    const float* Wi = (const float*)d_in[10]; const float* bi = (const float*)d_in[11];
    const float* W1 = (const float*)d_in[12]; const float* b1 = (const float*)d_in[13];
    const float* W2 = (const float*)d_in[14]; const float* b2 = (const float*)d_in[15];
    float* out = (float*)d_out;

    // function-attribute set (idempotent, not a stream op -> capture-safe)
    cudaFuncSetAttribute(gate_kernel, cudaFuncAttributeMaxDynamicSharedMemorySize,
                         (int)GATE_SMEM_BYTES);

    prep_transpose<<<dim3(24, 24, 6), dim3(32, 8)>>>(Wt, Wq, Wi, Wk, Wv, W1);
    proj_all<<<dim3(25, 12, 5), 128>>>(text, image, bt, bq, bi, bk, bv);
    gate_kernel<<<MGATE / 128, 512, GATE_SMEM_BYTES>>>(b1, W2, b2);
    attn_kernel<<<BS * NHEAD, 256>>>(out);
}

// round 4
// speedup vs baseline: 1.4063x; 1.4063x over previous
#include <cuda_runtime.h>
#include <cuda_fp16.h>
#include <math.h>
#include <stdint.h>

#define HDIM 768
#define NHEAD 12
#define DHEAD 64
#define BS 8
#define TLEN 64
#define ILEN 197
#define MTEXT (BS*TLEN)      // 512
#define MIMG  (BS*ILEN)      // 1576
#define MGATE (MTEXT*ILEN)   // 100864 = 788*128 exactly

// ---------------- scratch (static device memory; no allocation) ----------------
__device__ __half g_wT[6][HDIM*HDIM];       // transposed fp16 weights: 0:Wt 1:Wq 2:Wi 3:Wk 4:Wv 5:W1  ([N][K])
__device__ __half g_small[2][MTEXT*HDIM];   // 0: text_emb, 1: q
__device__ __half g_big[3][MIMG*HDIM];      // 0: image_emb, 1: k, 2: v
__device__ float  g_gate[MGATE];

// ---------------- mma.sync m16n8k16 fp16 -> fp32 ----------------
__device__ __forceinline__ void mma_f16(float c[4], uint32_t a0, uint32_t a1, uint32_t a2, uint32_t a3,
                                        uint32_t b0, uint32_t b1) {
    asm volatile(
        "mma.sync.aligned.m16n8k16.row.col.f32.f16.f16.f32 "
        "{%0,%1,%2,%3},{%4,%5,%6,%7},{%8,%9},{%0,%1,%2,%3};\n"
        : "+f"(c[0]), "+f"(c[1]), "+f"(c[2]), "+f"(c[3])
        : "r"(a0), "r"(a1), "r"(a2), "r"(a3), "r"(b0), "r"(b1));
}

// ---------------- prep: transpose + fp32->fp16 convert for 6 weight matrices ----------------
__global__ void prep_transpose(const float* __restrict__ Wt_, const float* __restrict__ Wq_,
                               const float* __restrict__ Wi_, const float* __restrict__ Wk_,
                               const float* __restrict__ Wv_, const float* __restrict__ W1_) {
    __shared__ float tile[32][33];
    int which = blockIdx.z;
    const float* src = (which == 0) ? Wt_ : (which == 1) ? Wq_ : (which == 2) ? Wi_
                     : (which == 3) ? Wk_ : (which == 4) ? Wv_ : W1_;
    __half* dst = g_wT[which];
    int k0 = blockIdx.y * 32, n0 = blockIdx.x * 32;
    #pragma unroll
    for (int r = threadIdx.y; r < 32; r += 8)
        tile[r][threadIdx.x] = src[(k0 + r) * HDIM + n0 + threadIdx.x];
    __syncthreads();
    #pragma unroll
    for (int r = threadIdx.y; r < 32; r += 8)
        dst[(size_t)(n0 + r) * HDIM + k0 + threadIdx.x] = __float2half(tile[threadIdx.x][r]);
}

// ---------------- fused projections: all 5 GEMMs in one launch ----------------
#define PJ_ST 72  // smem row stride in halves (64 + 8 pad)
__global__ __launch_bounds__(128) void proj_all(const float* __restrict__ text,
                                                const float* __restrict__ image,
                                                const float* __restrict__ bt,
                                                const float* __restrict__ bq,
                                                const float* __restrict__ bi,
                                                const float* __restrict__ bk,
                                                const float* __restrict__ bv) {
    int g = blockIdx.z;
    const float* A;
    const float* bias;
    __half* out;
    int M;
    if (g == 0)      { A = text;  bias = bt; out = g_small[0]; M = MTEXT; }
    else if (g == 1) { A = text;  bias = bq; out = g_small[1]; M = MTEXT; }
    else if (g == 2) { A = image; bias = bi; out = g_big[0];   M = MIMG; }
    else if (g == 3) { A = image; bias = bk; out = g_big[1];   M = MIMG; }
    else             { A = image; bias = bv; out = g_big[2];   M = MIMG; }
    int m0 = blockIdx.x * 64;
    if (m0 >= M) return;
    const __half* W = g_wT[g];

    __shared__ __half As[64 * PJ_ST];
    __shared__ __half Ws[64 * PJ_ST];         // [n][k]
    int n0 = blockIdx.y * 64;
    int tid = threadIdx.x, lane = tid & 31, warp = tid >> 5;
    int wm = (warp >> 1) * 32, wn = (warp & 1) * 32;

    float acc[2][4][4];
    #pragma unroll
    for (int i = 0; i < 2; i++)
        #pragma unroll
        for (int j = 0; j < 4; j++)
            #pragma unroll
            for (int x = 0; x < 4; x++) acc[i][j][x] = 0.f;

    for (int k0 = 0; k0 < HDIM; k0 += 64) {
        #pragma unroll
        for (int l = 0; l < 16; l++) {
            int idx = l * 128 + tid;
            int r = idx >> 5, c2 = idx & 31;
            int m = m0 + r;
            float2 v = (m < M) ? *(const float2*)(A + (size_t)m * HDIM + k0 + c2 * 2)
                               : make_float2(0.f, 0.f);
            *(__half2*)(As + r * PJ_ST + c2 * 2) = __floats2half2_rn(v.x, v.y);
        }
        #pragma unroll
        for (int l = 0; l < 16; l++) {
            int idx = l * 128 + tid;
            int r = idx >> 5, c2 = idx & 31;
            *(__half2*)(Ws + r * PJ_ST + c2 * 2) =
                *(const __half2*)(W + (size_t)(n0 + r) * HDIM + k0 + c2 * 2);
        }
        __syncthreads();
        #pragma unroll
        for (int kk = 0; kk < 64; kk += 16) {
            uint32_t af[2][4], bf[4][2];
            #pragma unroll
            for (int mt = 0; mt < 2; mt++) {
                const __half* base = As + (wm + mt * 16 + (lane >> 2)) * PJ_ST + kk + (lane & 3) * 2;
                af[mt][0] = *(const uint32_t*)(base);
                af[mt][1] = *(const uint32_t*)(base + 8 * PJ_ST);
                af[mt][2] = *(const uint32_t*)(base + 8);
                af[mt][3] = *(const uint32_t*)(base + 8 * PJ_ST + 8);
            }
            #pragma unroll
            for (int nt = 0; nt < 4; nt++) {
                const __half* base = Ws + (wn + nt * 8 + (lane >> 2)) * PJ_ST + kk + (lane & 3) * 2;
                bf[nt][0] = *(const uint32_t*)(base);
                bf[nt][1] = *(const uint32_t*)(base + 8);
            }
            #pragma unroll
            for (int mt = 0; mt < 2; mt++)
                #pragma unroll
                for (int nt = 0; nt < 4; nt++)
                    mma_f16(acc[mt][nt], af[mt][0], af[mt][1], af[mt][2], af[mt][3],
                            bf[nt][0], bf[nt][1]);
        }
        __syncthreads();
    }
    #pragma unroll
    for (int mt = 0; mt < 2; mt++) {
        int r0 = m0 + wm + mt * 16 + (lane >> 2);
        #pragma unroll
        for (int nt = 0; nt < 4; nt++) {
            int c = n0 + wn + nt * 8 + (lane & 3) * 2;
            float b0 = bias[c], b1v = bias[c + 1];
            if (r0 < M)
                *(__half2*)(out + (size_t)r0 * HDIM + c) =
                    __floats2half2_rn(acc[mt][nt][0] + b0, acc[mt][nt][1] + b1v);
            if (r0 + 8 < M)
                *(__half2*)(out + (size_t)(r0 + 8) * HDIM + c) =
                    __floats2half2_rn(acc[mt][nt][2] + b0, acc[mt][nt][3] + b1v);
        }
    }
}

// ---------------- fused gate kernel v2 (unchanged; passed @873us total) ----------------
#define AST 776                       // A row stride in halves (768 + 8)
#define WST 72                        // W tile row stride in halves
#define GATE_SMEM_BYTES (size_t)((128*AST + 128*WST) * sizeof(__half))
__global__ __launch_bounds__(512, 1) void gate_kernel(const float* __restrict__ b1,
                                                      const float* __restrict__ W2,
                                                      const float* __restrict__ pb2) {
    extern __shared__ __half dsm[];
    __half* As = dsm;                 // [128][AST]
    __half* Ws = dsm + 128 * AST;     // [128][WST]  ([n][k])
    __shared__ float s_z[128];

    int tid = threadIdx.x, lane = tid & 31, warp = tid >> 5;
    int m0 = blockIdx.x * 128;
    if (tid < 128) s_z[tid] = 0.f;

    const __half* W1t = g_wT[5];
    const __half* te = g_small[0];
    const __half* im = g_big[0];

    {
        int r = tid >> 2;
        int m = m0 + r;
        int tr = m / ILEN;
        int ir = m - tr * ILEN;
        const __half* trow = te + (size_t)tr * HDIM;
        const __half* irow = im + (size_t)((tr >> 6) * ILEN + ir) * HDIM;
        __half* arow = As + r * AST;
        int c0 = (tid & 3);
        #pragma unroll
        for (int j = 0; j < 96; j++) {
            int c2 = j * 4 + c0;
            __half2 tv = *(const __half2*)(trow + c2 * 2);
            __half2 iv = *(const __half2*)(irow + c2 * 2);
            *(__half2*)(arow + c2 * 2) = __hmul2(tv, iv);
        }
    }
    __syncthreads();

    int wm = (warp >> 2) * 32, wn = (warp & 3) * 32;
    float zp[4] = {0.f, 0.f, 0.f, 0.f};

    for (int n0 = 0; n0 < HDIM; n0 += 128) {
        float acc[2][4][4];
        #pragma unroll
        for (int i = 0; i < 2; i++)
            #pragma unroll
            for (int j = 0; j < 4; j++)
                #pragma unroll
                for (int x = 0; x < 4; x++) acc[i][j][x] = 0.f;

        uint32_t wreg[8];
        #pragma unroll
        for (int l = 0; l < 8; l++) {
            int idx = l * 512 + tid;
            int r = idx >> 5, c2 = idx & 31;
            wreg[l] = *(const uint32_t*)(W1t + (size_t)(n0 + r) * HDIM + c2 * 2);
        }

        for (int k0 = 0; k0 < HDIM; k0 += 64) {
            #pragma unroll
            for (int l = 0; l < 8; l++) {
                int idx = l * 512 + tid;
                int r = idx >> 5, c2 = idx & 31;
                *(uint32_t*)(Ws + r * WST + c2 * 2) = wreg[l];
            }
            __syncthreads();
            if (k0 + 64 < HDIM) {
                #pragma unroll
                for (int l = 0; l < 8; l++) {
                    int idx = l * 512 + tid;
                    int r = idx >> 5, c2 = idx & 31;
                    wreg[l] = *(const uint32_t*)(W1t + (size_t)(n0 + r) * HDIM + (k0 + 64) + c2 * 2);
                }
            }
            #pragma unroll
            for (int kk = 0; kk < 64; kk += 16) {
                uint32_t af[2][4], bf[4][2];
                #pragma unroll
                for (int mt = 0; mt < 2; mt++) {
                    const __half* base = As + (wm + mt * 16 + (lane >> 2)) * AST + (k0 + kk) + (lane & 3) * 2;
                    af[mt][0] = *(const uint32_t*)(base);
                    af[mt][1] = *(const uint32_t*)(base + 8 * AST);
                    af[mt][2] = *(const uint32_t*)(base + 8);
                    af[mt][3] = *(const uint32_t*)(base + 8 * AST + 8);
                }
                #pragma unroll
                for (int nt = 0; nt < 4; nt++) {
                    const __half* base = Ws + (wn + nt * 8 + (lane >> 2)) * WST + kk + (lane & 3) * 2;
                    bf[nt][0] = *(const uint32_t*)(base);
                    bf[nt][1] = *(const uint32_t*)(base + 8);
                }
                #pragma unroll
                for (int mt = 0; mt < 2; mt++)
                    #pragma unroll
                    for (int nt = 0; nt < 4; nt++)
                        mma_f16(acc[mt][nt], af[mt][0], af[mt][1], af[mt][2], af[mt][3],
                                bf[nt][0], bf[nt][1]);
            }
            __syncthreads();
        }
        #pragma unroll
        for (int mt = 0; mt < 2; mt++) {
            #pragma unroll
            for (int nt = 0; nt < 4; nt++) {
                int c = n0 + wn + nt * 8 + (lane & 3) * 2;
                float bb0 = __ldg(b1 + c), bb1 = __ldg(b1 + c + 1);
                float w0 = __ldg(W2 + c), w1 = __ldg(W2 + c + 1);
                float y00 = fmaxf(acc[mt][nt][0] + bb0, 0.f);
                float y01 = fmaxf(acc[mt][nt][1] + bb1, 0.f);
                float y10 = fmaxf(acc[mt][nt][2] + bb0, 0.f);
                float y11 = fmaxf(acc[mt][nt][3] + bb1, 0.f);
                zp[2 * mt + 0] += y00 * w0 + y01 * w1;
                zp[2 * mt + 1] += y10 * w0 + y11 * w1;
            }
        }
    }
    int r0 = wm + (lane >> 2);
    atomicAdd(&s_z[r0],      zp[0]);
    atomicAdd(&s_z[r0 + 8],  zp[1]);
    atomicAdd(&s_z[r0 + 16], zp[2]);
    atomicAdd(&s_z[r0 + 24], zp[3]);
    __syncthreads();
    if (tid < 128) {
        float z = s_z[tid] + pb2[0];
        g_gate[m0 + tid] = 1.f / (1.f + __expf(-z));
    }
}

// ---------------- attention v2: smem-staged K/V, 768 CTAs, broken dep chains ----------------
// grid (96, 8): blockIdx.x = b*NHEAD+h, blockIdx.y = t-chunk of 8. Warp w owns t = chunk*8+w.
#define AT_ST 66   // 33 words (odd) -> conflict-free row-major lane access
#define ATTN_SMEM_BYTES (size_t)(2 * ILEN * AT_ST * sizeof(__half))
__global__ __launch_bounds__(256) void attn_kernel(float* __restrict__ out) {
    extern __shared__ __half kvsm[];
    __half* ks = kvsm;                  // [ILEN][AT_ST]
    __half* vs = kvsm + ILEN * AT_ST;   // [ILEN][AT_ST]
    __shared__ float ps[8][ILEN + 1];
    __shared__ float qs[8][DHEAD];

    int tid = threadIdx.x, lane = tid & 31, warp = tid >> 5;
    int bh = blockIdx.x;
    int b = bh / NHEAD, h = bh % NHEAD;
    const __half* kg = g_big[1] + (size_t)b * ILEN * HDIM + h * DHEAD;
    const __half* vg = g_big[2] + (size_t)b * ILEN * HDIM + h * DHEAD;
    const __half* qg = g_small[1];

    // stage K and V tiles (each 197 x 32 half2)
    for (int idx = tid; idx < ILEN * 32; idx += 256) {
        int i = idx >> 5, c2 = idx & 31;
        *(__half2*)(ks + i * AT_ST + c2 * 2) = *(const __half2*)(kg + (size_t)i * HDIM + c2 * 2);
        *(__half2*)(vs + i * AT_ST + c2 * 2) = *(const __half2*)(vg + (size_t)i * HDIM + c2 * 2);
    }
    int t = blockIdx.y * 8 + warp;
    // q row -> smem (fp32)
    {
        __half2 qv = *(const __half2*)(qg + (size_t)(b * TLEN + t) * HDIM + h * DHEAD + lane * 2);
        qs[warp][lane * 2] = __low2float(qv);
        qs[warp][lane * 2 + 1] = __high2float(qv);
    }
    __syncthreads();

    // scores: lanes stride i; 4 accumulators break the FFMA chain
    float sv[7];
    float smax = -1e30f;
    #pragma unroll
    for (int ii = 0; ii < 7; ii++) {
        int i = lane + ii * 32;
        float s = -1e30f;
        if (i < ILEN) {
            const __half* krow = ks + i * AT_ST;
            float a0 = 0.f, a1 = 0.f, a2 = 0.f, a3 = 0.f;
            #pragma unroll
            for (int d2 = 0; d2 < 32; d2 += 4) {
                __half2 k0 = *(const __half2*)(krow + d2 * 2);
                __half2 k1 = *(const __half2*)(krow + d2 * 2 + 2);
                __half2 k2 = *(const __half2*)(krow + d2 * 2 + 4);
                __half2 k3 = *(const __half2*)(krow + d2 * 2 + 6);
                a0 += qs[warp][d2 * 2]     * __low2float(k0) + qs[warp][d2 * 2 + 1] * __high2float(k0);
                a1 += qs[warp][d2 * 2 + 2] * __low2float(k1) + qs[warp][d2 * 2 + 3] * __high2float(k1);
                a2 += qs[warp][d2 * 2 + 4] * __low2float(k2) + qs[warp][d2 * 2 + 5] * __high2float(k2);
                a3 += qs[warp][d2 * 2 + 6] * __low2float(k3) + qs[warp][d2 * 2 + 7] * __high2float(k3);
            }
            s = (a0 + a1 + a2 + a3) * 0.125f;
        }
        sv[ii] = s;
        smax = fmaxf(smax, s);
    }
    #pragma unroll
    for (int o = 16; o; o >>= 1) smax = fmaxf(smax, __shfl_xor_sync(0xffffffffu, smax, o));
    float ssum = 0.f;
    #pragma unroll
    for (int ii = 0; ii < 7; ii++) {
        int i = lane + ii * 32;
        float e = (i < ILEN) ? __expf(sv[ii] - smax) : 0.f;
        sv[ii] = e;
        ssum += e;
    }
    #pragma unroll
    for (int o = 16; o; o >>= 1) ssum += __shfl_xor_sync(0xffffffffu, ssum, o);
    float inv = 1.f / ssum;
    int gbase = (b * TLEN + t) * ILEN;
    #pragma unroll
    for (int ii = 0; ii < 7; ii++) {
        int i = lane + ii * 32;
        if (i < ILEN) ps[warp][i] = sv[ii] * inv * g_gate[gbase + i];
    }
    __syncwarp();

    // ctx: lane owns d pair; 2-way i unroll + split accumulators
    float a0 = 0.f, a1 = 0.f, c0 = 0.f, c1 = 0.f;
    #pragma unroll 2
    for (int i = 0; i < ILEN - 1; i += 2) {
        float p0 = ps[warp][i], p1 = ps[warp][i + 1];
        __half2 v0 = *(const __half2*)(vs + i * AT_ST + lane * 2);
        __half2 v1 = *(const __half2*)(vs + (i + 1) * AT_ST + lane * 2);
        a0 += p0 * __low2float(v0);
        a1 += p0 * __high2float(v0);
        c0 += p1 * __low2float(v1);
        c1 += p1 * __high2float(v1);
    }
    {
        float p = ps[warp][ILEN - 1];
        __half2 v2 = *(const __half2*)(vs + (ILEN - 1) * AT_ST + lane * 2);
        a0 += p * __low2float(v2);
        a1 += p * __high2float(v2);
    }
    size_t obase = (size_t)(b * TLEN + t) * HDIM + h * DHEAD + lane * 2;
    out[obase] = a0 + c0;
    out[obase + 1] = a1 + c1;
}

// ---------------- launch ----------------
extern "C" void kernel_launch(void* const* d_in, const int* in_sizes, int n_in,
                              void* d_out, int out_size) {
    (void)in_sizes; (void)n_in; (void)out_size;
    const float* text  = (const float*)d_in[0];
    const float* image = (const float*)d_in[1];
    const float* Wq = (const float*)d_in[2];  const float* bq = (const float*)d_in[3];
    const float* Wk = (const float*)d_in[4];  const float* bk = (const float*)d_in[5];
    const float* Wv = (const float*)d_in[6];  const float* bv = (const float*)d_in[7];
    const float* Wt = (const float*)d_in[8];  const float* bt = (const float*)d_in[9];
    const float* Wi = (const float*)d_in[10]; const float* bi = (const float*)d_in[11];
    const float* W1 = (const float*)d_in[12]; const float* b1 = (const float*)d_in[13];
    const float* W2 = (const float*)d_in[14]; const float* b2 = (const float*)d_in[15];
    float* out = (float*)d_out;

    cudaFuncSetAttribute(gate_kernel, cudaFuncAttributeMaxDynamicSharedMemorySize,
                         (int)GATE_SMEM_BYTES);
    cudaFuncSetAttribute(attn_kernel, cudaFuncAttributeMaxDynamicSharedMemorySize,
                         (int)ATTN_SMEM_BYTES);

    prep_transpose<<<dim3(24, 24, 6), dim3(32, 8)>>>(Wt, Wq, Wi, Wk, Wv, W1);
    proj_all<<<dim3(25, 12, 5), 128>>>(text, image, bt, bq, bi, bk, bv);
    gate_kernel<<<MGATE / 128, 512, GATE_SMEM_BYTES>>>(b1, W2, b2);
    attn_kernel<<<dim3(BS * NHEAD, 8), 256, ATTN_SMEM_BYTES>>>(out);
}